// round 2
// baseline (speedup 1.0000x reference)
#include <cuda_runtime.h>
#include <cuda_bf16.h>

// Problem constants
#define H 128
#define W 128
#define HW (H * W)          // 16384
#define C 32
#define KK 81               // 9x9
#define KS 9
#define DIL 2
#define PAD 8

#define PSTRIDE 144         // padded row stride (W + 2*PAD)
#define PPLANE (PSTRIDE * PSTRIDE)  // 20736 floats per channel plane

typedef unsigned long long ull;

// Scratch (device globals; no allocations allowed)
__device__ __align__(16) float g_k[KK * HW];        // guidance kernel [ij][p]
__device__ __align__(16) float g_xpad[C * PPLANE];  // padded x
__device__ __align__(16) float g_hpad[C * PPLANE];  // padded layer-1 output
__device__ __align__(16) float g_w1t[KK * C * C];   // W1 transposed [ij][c][o]
__device__ __align__(16) float g_w2t[KK * C * C];   // W2 transposed [ij][c][o]

// ---- packed f32x2 helpers (sm_103a) ---------------------------------------
__device__ __forceinline__ ull pack2(float v) {
    ull r; asm("mov.b64 %0, {%1, %1};" : "=l"(r) : "f"(v)); return r;
}
__device__ __forceinline__ void fma2(ull& acc, ull a, ull b) {
    asm("fma.rn.f32x2 %0, %1, %2, %0;" : "+l"(acc) : "l"(a), "l"(b));
}
__device__ __forceinline__ ull mul2(ull a, ull b) {
    ull r; asm("mul.rn.f32x2 %0, %1, %2;" : "=l"(r) : "l"(a), "l"(b)); return r;
}
__device__ __forceinline__ float2 unpack2(ull v) {
    float2 f; asm("mov.b64 {%0, %1}, %2;" : "=f"(f.x), "=f"(f.y) : "l"(v)); return f;
}

// ---------------------------------------------------------------------------
// Transpose weights (O,C,9,9) -> (81, C, O): per-offset 32x32 slices
// contiguous, output pairs (o, o+1) adjacent for f32x2.
// ---------------------------------------------------------------------------
__global__ void prep_w(const float* __restrict__ W1, const float* __restrict__ W2) {
    int t = blockIdx.x * blockDim.x + threadIdx.x;
    const int N = KK * C * C;  // 82944
    if (t >= 2 * N) return;
    const float* Wsrc = (t < N) ? W1 : W2;
    float* Wdst = (t < N) ? g_w1t : g_w2t;
    int e = (t < N) ? t : (t - N);
    int ij = e >> 10;
    int c = (e >> 5) & 31;
    int o = e & 31;
    Wdst[e] = Wsrc[o * (C * KK) + c * KK + ij];
}

// ---------------------------------------------------------------------------
// Pad x into g_xpad (zero borders) and zero g_hpad borders.
// ---------------------------------------------------------------------------
__global__ void pad_x(const float* __restrict__ x) {
    int t = blockIdx.x * blockDim.x + threadIdx.x;
    const int N = C * PPLANE;
    if (t >= N) return;
    int c = t / PPLANE;
    int rem = t - c * PPLANE;
    int r = rem / PSTRIDE;
    int col = rem - r * PSTRIDE;
    bool interior = (r >= PAD) && (r < PAD + H) && (col >= PAD) && (col < PAD + W);
    if (interior) {
        g_xpad[t] = x[c * HW + (r - PAD) * W + (col - PAD)];
    } else {
        g_xpad[t] = 0.f;
        g_hpad[t] = 0.f;   // layer-1 writes only the interior
    }
}

// ---------------------------------------------------------------------------
// Guidance kernel: k[ij][p] = exp(-0.5 * sum_c (xpad_f[...] - f[c,p])^2)
// with f read from the (already padded) feature planes? -> use original f.
// ---------------------------------------------------------------------------
__global__ void compute_k(const float* __restrict__ f) {
    int p = blockIdx.x * blockDim.x + threadIdx.x;
    int h = p >> 7;
    int w = p & 127;

    float fc[C];
#pragma unroll
    for (int c = 0; c < C; c++) fc[c] = __ldg(f + c * HW + p);
    float normc = 0.f;
#pragma unroll
    for (int c = 0; c < C; c++) normc = fmaf(fc[c], fc[c], normc);

    int ij0 = blockIdx.y * 27;
#pragma unroll 1
    for (int s = 0; s < 27; s++) {
        int ij = ij0 + s;
        int hh = h + (ij / KS) * DIL - PAD;
        int ww = w + (ij % KS) * DIL - PAD;
        float acc;
        if ((unsigned)hh < (unsigned)H && (unsigned)ww < (unsigned)W) {
            const float* fp = f + hh * W + ww;
            acc = 0.f;
#pragma unroll
            for (int c = 0; c < C; c++) {
                float d = __ldg(fp + c * HW) - fc[c];
                acc = fmaf(d, d, acc);
            }
        } else {
            acc = normc;
        }
        g_k[ij * HW + p] = __expf(-0.5f * acc);
    }
}

// ---------------------------------------------------------------------------
// PAC conv, factored:  out[o][p] = b[o] + sum_ij k[ij][p] * (sum_c W[ij][c][o]
//                                   * xpad[c][p + off(ij)])
// Block: 256 thr = 64 pixels x 4 output groups. Thread: 1 pixel, 8 outputs as
// 4 f32x2 pairs. Weights staged in smem (27 slices = 108KB per chunk).
// Inner c-loop: 1 LDG + 1 pack + 4 LDS.64 + 4 FFMA2 — branch-free.
// ---------------------------------------------------------------------------
#define CHUNK 27

__global__ void pacconv2(const float* __restrict__ xpad,
                         const float* __restrict__ Wt,
                         const float* __restrict__ bias,
                         float* __restrict__ out, int oplane, int orow) {
    extern __shared__ float Wsm[];  // CHUNK * 1024 floats
    int tid = threadIdx.x;
    int og = tid >> 6;                       // 0..3 -> outputs og*8 .. og*8+7
    int p = blockIdx.x * 64 + (tid & 63);
    int h = p >> 7;
    int w = p & 127;

    const float* xbase = xpad + h * PSTRIDE + w;   // neighbor (i,j): + (2i)*144 + 2j
    const float* kp = g_k + p;

    ull acc0, acc1, acc2, acc3;
    {
        const float* bp = bias + og * 8;
        float2 t;
        t.x = __ldg(bp + 0); t.y = __ldg(bp + 1);
        asm("mov.b64 %0, {%1, %2};" : "=l"(acc0) : "f"(t.x), "f"(t.y));
        t.x = __ldg(bp + 2); t.y = __ldg(bp + 3);
        asm("mov.b64 %0, {%1, %2};" : "=l"(acc1) : "f"(t.x), "f"(t.y));
        t.x = __ldg(bp + 4); t.y = __ldg(bp + 5);
        asm("mov.b64 %0, {%1, %2};" : "=l"(acc2) : "f"(t.x), "f"(t.y));
        t.x = __ldg(bp + 6); t.y = __ldg(bp + 7);
        asm("mov.b64 %0, {%1, %2};" : "=l"(acc3) : "f"(t.x), "f"(t.y));
    }

#pragma unroll 1
    for (int chunk = 0; chunk < 3; chunk++) {
        __syncthreads();
        {   // cooperative stage of 27 weight slices (27648 floats)
            const float4* src = (const float4*)(Wt + chunk * CHUNK * 1024);
            float4* dst = (float4*)Wsm;
#pragma unroll
            for (int r = 0; r < CHUNK; r++) dst[r * 256 + tid] = src[r * 256 + tid];
        }
        __syncthreads();

#pragma unroll 1
        for (int s = 0; s < CHUNK; s++) {
            int ij = chunk * CHUNK + s;
            int di = ij / KS, dj = ij - di * KS;
            const float* xp = xbase + (di * DIL) * PSTRIDE + dj * DIL;
            const ull* wrow = ((const ull*)(Wsm + s * 1024)) + og * 4;

            ull in0, in1, in2, in3;
            {
                ull x2 = pack2(__ldg(xp));
                in0 = mul2(x2, wrow[0]);
                in1 = mul2(x2, wrow[1]);
                in2 = mul2(x2, wrow[2]);
                in3 = mul2(x2, wrow[3]);
            }
#pragma unroll
            for (int c = 1; c < C; c++) {
                ull x2 = pack2(__ldg(xp + c * PPLANE));
                fma2(in0, x2, wrow[c * 16 + 0]);
                fma2(in1, x2, wrow[c * 16 + 1]);
                fma2(in2, x2, wrow[c * 16 + 2]);
                fma2(in3, x2, wrow[c * 16 + 3]);
            }
            ull k2 = pack2(__ldg(kp + ij * HW));
            fma2(acc0, k2, in0);
            fma2(acc1, k2, in1);
            fma2(acc2, k2, in2);
            fma2(acc3, k2, in3);
        }
    }

    float* op = out + h * orow + w;
    int ob = og * 8;
    float2 r;
    r = unpack2(acc0); op[(ob + 0) * oplane] = r.x; op[(ob + 1) * oplane] = r.y;
    r = unpack2(acc1); op[(ob + 2) * oplane] = r.x; op[(ob + 3) * oplane] = r.y;
    r = unpack2(acc2); op[(ob + 4) * oplane] = r.x; op[(ob + 5) * oplane] = r.y;
    r = unpack2(acc3); op[(ob + 6) * oplane] = r.x; op[(ob + 7) * oplane] = r.y;
}

// ---------------------------------------------------------------------------
extern "C" void kernel_launch(void* const* d_in, const int* in_sizes, int n_in,
                              void* d_out, int out_size) {
    const float* x = (const float*)d_in[0];
    const float* f = (const float*)d_in[1];
    const float* W1 = (const float*)d_in[2];
    const float* b1 = (const float*)d_in[3];
    const float* W2 = (const float*)d_in[4];
    const float* b2 = (const float*)d_in[5];
    float* out = (float*)d_out;

    float* xpad;  cudaGetSymbolAddress((void**)&xpad, g_xpad);
    float* hpad;  cudaGetSymbolAddress((void**)&hpad, g_hpad);
    float* w1t;   cudaGetSymbolAddress((void**)&w1t, g_w1t);
    float* w2t;   cudaGetSymbolAddress((void**)&w2t, g_w2t);

    const int smem = CHUNK * 1024 * sizeof(float);  // 110592 bytes
    cudaFuncSetAttribute(pacconv2, cudaFuncAttributeMaxDynamicSharedMemorySize, smem);

    // 1. transpose weights
    prep_w<<<(2 * KK * C * C + 255) / 256, 256>>>(W1, W2);

    // 2. pad x, zero hpad borders
    pad_x<<<(C * PPLANE + 255) / 256, 256>>>(x);

    // 3. guidance kernel
    dim3 gk(HW / 256, 3);
    compute_k<<<gk, 256>>>(f);

    // 4. layer 1: xpad -> hpad interior
    pacconv2<<<HW / 64, 256, smem>>>(xpad, w1t, b1,
                                     hpad + PAD * PSTRIDE + PAD, PPLANE, PSTRIDE);

    // 5. layer 2: hpad -> out
    pacconv2<<<HW / 64, 256, smem>>>(hpad, w2t, b2, out, HW, W);
}

// round 3
// speedup vs baseline: 1.4303x; 1.4303x over previous
#include <cuda_runtime.h>
#include <cuda_bf16.h>

// Problem constants
#define H 128
#define W 128
#define HW (H * W)          // 16384
#define C 32
#define KK 81               // 9x9
#define KKP 84              // padded to 6 chunks of 14
#define KS 9
#define DIL 2
#define PAD 8

#define PSTRIDE 144                  // padded row stride
#define PPLANE (PSTRIDE * PSTRIDE)   // 20736 floats per channel plane

#define CHUNKW 14                    // weight slices per smem chunk
#define NCHUNK 6                     // 6*14 = 84

typedef unsigned long long ull;

// Scratch (device globals; zero-initialized at load)
__device__ __align__(16) float g_k[KK * HW];         // guidance kernel [ij][p]
__device__ __align__(16) float g_xpad[C * PPLANE];   // padded x
__device__ __align__(16) float g_hpad[C * PPLANE];   // padded layer-1 output
__device__ __align__(16) float g_w1t[KKP * C * C];   // W1 transposed [ij][c][o]
__device__ __align__(16) float g_w2t[KKP * C * C];   // W2 transposed [ij][c][o]

// ---- packed f32x2 helpers (sm_103a) ---------------------------------------
__device__ __forceinline__ ull pack2(float v) {
    ull r; asm("mov.b64 %0, {%1, %1};" : "=l"(r) : "f"(v)); return r;
}
__device__ __forceinline__ void fma2(ull& acc, ull a, ull b) {
    asm("fma.rn.f32x2 %0, %1, %2, %0;" : "+l"(acc) : "l"(a), "l"(b));
}
__device__ __forceinline__ float2 unpack2(ull v) {
    float2 f; asm("mov.b64 {%0, %1}, %2;" : "=f"(f.x), "=f"(f.y) : "l"(v)); return f;
}

// ---------------------------------------------------------------------------
// Transpose weights (O,C,9,9) -> (84, C, O); slices 81..83 zeroed.
// ---------------------------------------------------------------------------
__global__ void prep_w(const float* __restrict__ W1, const float* __restrict__ W2) {
    int t = blockIdx.x * blockDim.x + threadIdx.x;
    const int N = KKP * C * C;  // 86016
    if (t >= 2 * N) return;
    const float* Wsrc = (t < N) ? W1 : W2;
    float* Wdst = (t < N) ? g_w1t : g_w2t;
    int e = (t < N) ? t : (t - N);
    int ij = e >> 10;
    int c = (e >> 5) & 31;
    int o = e & 31;
    Wdst[e] = (ij < KK) ? Wsrc[o * (C * KK) + c * KK + ij] : 0.f;
}

// ---------------------------------------------------------------------------
// Pad x into g_xpad (zero borders) and zero g_hpad borders.
// ---------------------------------------------------------------------------
__global__ void pad_x(const float* __restrict__ x) {
    int t = blockIdx.x * blockDim.x + threadIdx.x;
    const int N = C * PPLANE;
    if (t >= N) return;
    int c = t / PPLANE;
    int rem = t - c * PPLANE;
    int r = rem / PSTRIDE;
    int col = rem - r * PSTRIDE;
    bool interior = (r >= PAD) && (r < PAD + H) && (col >= PAD) && (col < PAD + W);
    if (interior) {
        g_xpad[t] = x[c * HW + (r - PAD) * W + (col - PAD)];
    } else {
        g_xpad[t] = 0.f;
        g_hpad[t] = 0.f;   // pacconv writes only the interior
    }
}

// ---------------------------------------------------------------------------
// Guidance kernel: k[ij][p] = exp(-0.5 * sum_c (f_nbr - f_c)^2); OOB -> ||f_c||^2
// ---------------------------------------------------------------------------
__global__ void compute_k(const float* __restrict__ f) {
    int p = blockIdx.x * blockDim.x + threadIdx.x;
    int h = p >> 7;
    int w = p & 127;

    float fc[C];
#pragma unroll
    for (int c = 0; c < C; c++) fc[c] = __ldg(f + c * HW + p);
    float normc = 0.f;
#pragma unroll
    for (int c = 0; c < C; c++) normc = fmaf(fc[c], fc[c], normc);

    int ij0 = blockIdx.y * 27;
#pragma unroll 1
    for (int s = 0; s < 27; s++) {
        int ij = ij0 + s;
        int hh = h + (ij / KS) * DIL - PAD;
        int ww = w + (ij % KS) * DIL - PAD;
        float acc;
        if ((unsigned)hh < (unsigned)H && (unsigned)ww < (unsigned)W) {
            const float* fp = f + hh * W + ww;
            acc = 0.f;
#pragma unroll
            for (int c = 0; c < C; c++) {
                float d = __ldg(fp + c * HW) - fc[c];
                acc = fmaf(d, d, acc);
            }
        } else {
            acc = normc;
        }
        g_k[ij * HW + p] = __expf(-0.5f * acc);
    }
}

// ---------------------------------------------------------------------------
// PAC conv: out[o][p] = b[o] + sum_ij k[ij][p] * sum_c W[ij][c][o]*xpad[c][p+off]
// Block: 256 thr = 64 px (one row segment) x 4 output groups of 8.
// Per-ij: cooperative z-stage (double-buffered) -> smem-only consume loop.
// ---------------------------------------------------------------------------
__global__ void pacconv3(const float* __restrict__ xpad,
                         const float* __restrict__ Wt,
                         const float* __restrict__ bias,
                         float* __restrict__ out, int oplane, int orow) {
    extern __shared__ float smem[];
    float* Wsm = smem;                  // CHUNKW*1024 = 14336 floats
    float* Zs = smem + CHUNKW * 1024;   // 2 * 2048 floats

    int tid = threadIdx.x;
    int og = tid >> 6;                  // 0..3 -> outputs og*8..og*8+7
    int px = tid & 63;
    int h = blockIdx.x >> 1;
    int w0 = (blockIdx.x & 1) << 6;
    int p = h * W + w0 + px;

    const float* xb = xpad + h * PSTRIDE + w0 + px;  // + c*PPLANE + off
    const float* kp = g_k + p;

    ull acc0, acc1, acc2, acc3;
    {
        const float* bp = bias + og * 8;
        float a, b;
        a = __ldg(bp + 0); b = __ldg(bp + 1);
        asm("mov.b64 %0, {%1, %2};" : "=l"(acc0) : "f"(a), "f"(b));
        a = __ldg(bp + 2); b = __ldg(bp + 3);
        asm("mov.b64 %0, {%1, %2};" : "=l"(acc1) : "f"(a), "f"(b));
        a = __ldg(bp + 4); b = __ldg(bp + 5);
        asm("mov.b64 %0, {%1, %2};" : "=l"(acc2) : "f"(a), "f"(b));
        a = __ldg(bp + 6); b = __ldg(bp + 7);
        asm("mov.b64 %0, {%1, %2};" : "=l"(acc3) : "f"(a), "f"(b));
    }

    // stage z for ij into buffer buf: thread covers c = og+4i at its pixel
    auto stage = [&](int buf, int ij) {
        int ijc = (ij < KK) ? ij : (KK - 1);            // clamp (k=0 beyond 80)
        int di = ijc / KS, dj = ijc - di * KS;
        const float* sp = xb + di * DIL * PSTRIDE + dj * DIL;
        float* zd = Zs + buf * 2048 + og * 64 + px;
#pragma unroll
        for (int i = 0; i < 8; i++)
            zd[i * 4 * 64] = __ldg(sp + (i * 4 + og) * PPLANE);
    };

    stage(0, 0);

#pragma unroll 1
    for (int chunk = 0; chunk < NCHUNK; chunk++) {
        __syncthreads();   // consumers done with prev weights / z0 staged
        {   // stage 14 weight slices: 3584 float4 / 256 thr = 14 each
            const float4* src = (const float4*)(Wt + chunk * CHUNKW * 1024);
            float4* dst = (float4*)Wsm;
#pragma unroll
            for (int r = 0; r < CHUNKW; r++) dst[r * 256 + tid] = src[r * 256 + tid];
        }
        __syncthreads();

#pragma unroll 1
        for (int s = 0; s < CHUNKW; s++) {
            int t = chunk * CHUNKW + s;
            int buf = t & 1;

            float kv = (t < KK) ? __ldg(kp + t * HW) : 0.f;  // used ~200 instr later

            if (t + 1 < KKP) stage(buf ^ 1, t + 1);

            const ull* wrow = ((const ull*)(Wsm + s * 1024)) + og * 4;
            const float* zc = Zs + buf * 2048 + px;

            ull in0, in1, in2, in3;
            {
                ull z2 = pack2(zc[0]);
                asm("mul.rn.f32x2 %0, %1, %2;" : "=l"(in0) : "l"(z2), "l"(wrow[0]));
                asm("mul.rn.f32x2 %0, %1, %2;" : "=l"(in1) : "l"(z2), "l"(wrow[1]));
                asm("mul.rn.f32x2 %0, %1, %2;" : "=l"(in2) : "l"(z2), "l"(wrow[2]));
                asm("mul.rn.f32x2 %0, %1, %2;" : "=l"(in3) : "l"(z2), "l"(wrow[3]));
            }
#pragma unroll
            for (int c = 1; c < C; c++) {
                ull z2 = pack2(zc[c * 64]);
                fma2(in0, z2, wrow[c * 16 + 0]);
                fma2(in1, z2, wrow[c * 16 + 1]);
                fma2(in2, z2, wrow[c * 16 + 2]);
                fma2(in3, z2, wrow[c * 16 + 3]);
            }
            ull k2 = pack2(kv);
            fma2(acc0, k2, in0);
            fma2(acc1, k2, in1);
            fma2(acc2, k2, in2);
            fma2(acc3, k2, in3);

            __syncthreads();   // z buffer reuse fence
        }
    }

    float* op = out + h * orow + w0 + px;
    int ob = og * 8;
    float2 r;
    r = unpack2(acc0); op[(ob + 0) * oplane] = r.x; op[(ob + 1) * oplane] = r.y;
    r = unpack2(acc1); op[(ob + 2) * oplane] = r.x; op[(ob + 3) * oplane] = r.y;
    r = unpack2(acc2); op[(ob + 4) * oplane] = r.x; op[(ob + 5) * oplane] = r.y;
    r = unpack2(acc3); op[(ob + 6) * oplane] = r.x; op[(ob + 7) * oplane] = r.y;
}

// ---------------------------------------------------------------------------
extern "C" void kernel_launch(void* const* d_in, const int* in_sizes, int n_in,
                              void* d_out, int out_size) {
    const float* x = (const float*)d_in[0];
    const float* f = (const float*)d_in[1];
    const float* W1 = (const float*)d_in[2];
    const float* b1 = (const float*)d_in[3];
    const float* W2 = (const float*)d_in[4];
    const float* b2 = (const float*)d_in[5];
    float* out = (float*)d_out;

    float* xpad;  cudaGetSymbolAddress((void**)&xpad, g_xpad);
    float* hpad;  cudaGetSymbolAddress((void**)&hpad, g_hpad);
    float* w1t;   cudaGetSymbolAddress((void**)&w1t, g_w1t);
    float* w2t;   cudaGetSymbolAddress((void**)&w2t, g_w2t);

    const int smem = (CHUNKW * 1024 + 2 * 2048) * sizeof(float);  // 73728
    cudaFuncSetAttribute(pacconv3, cudaFuncAttributeMaxDynamicSharedMemorySize, smem);

    // 1. transpose weights (84 padded slices each)
    prep_w<<<(2 * KKP * C * C + 255) / 256, 256>>>(W1, W2);

    // 2. pad x, zero hpad borders
    pad_x<<<(C * PPLANE + 255) / 256, 256>>>(x);

    // 3. guidance kernel
    dim3 gk(HW / 256, 3);
    compute_k<<<gk, 256>>>(f);

    // 4. layer 1: xpad -> hpad interior
    pacconv3<<<HW / 64, 256, smem>>>(xpad, w1t, b1,
                                     hpad + PAD * PSTRIDE + PAD, PPLANE, PSTRIDE);

    // 5. layer 2: hpad -> out
    pacconv3<<<HW / 64, 256, smem>>>(hpad, w2t, b2, out, HW, W);
}

// round 5
// speedup vs baseline: 1.6216x; 1.1337x over previous
#include <cuda_runtime.h>
#include <cuda_bf16.h>
#include <cstdint>

// Problem constants
#define H 128
#define W 128
#define HW (H * W)          // 16384
#define C 32
#define KK 81               // 9x9
#define KS 9
#define DIL 2
#define PAD 8

#define PSTRIDE 144                  // padded row stride
#define PPLANE (PSTRIDE * PSTRIDE)   // 20736 floats per channel plane

// ---------------- device scratch (no allocations allowed) -------------------
__device__ __align__(16) float    g_k[KK * HW];        // guidance kernel [ij][p]
__device__ __align__(16) float    g_xpad[C * PPLANE];  // padded x
__device__ __align__(16) float    g_hpad[C * PPLANE];  // padded layer-1 output
// B fragments, prepacked per (ij, lane) in mma.sync m16n8k16 layout:
//   word index = ij*1024 + lane*32 + [hi:0 / lo:16] + s*8 + j*2 + r
__device__ __align__(16) uint32_t g_wf1[KK * 1024];
__device__ __align__(16) uint32_t g_wf2[KK * 1024];

// ---------------- helpers ---------------------------------------------------
__device__ __forceinline__ uint32_t cvt_bf2(float hi, float lo) {
    uint32_t r;
    asm("cvt.rn.bf16x2.f32 %0, %1, %2;" : "=r"(r) : "f"(hi), "f"(lo));
    return r;  // low half <- lo, high half <- hi
}

__device__ __forceinline__ void mma16816(float* d,
                                         uint32_t a0, uint32_t a1, uint32_t a2, uint32_t a3,
                                         uint32_t b0, uint32_t b1) {
    asm volatile(
        "mma.sync.aligned.m16n8k16.row.col.f32.bf16.bf16.f32 "
        "{%0,%1,%2,%3}, {%4,%5,%6,%7}, {%8,%9}, {%0,%1,%2,%3};"
        : "+f"(d[0]), "+f"(d[1]), "+f"(d[2]), "+f"(d[3])
        : "r"(a0), "r"(a1), "r"(a2), "r"(a3), "r"(b0), "r"(b1));
}

// ---------------- prep: weights -> per-lane B fragments (hi/lo bf16) --------
// For (ij, lane): g=lane>>2, t=lane&3. Fragment (s,j,r): o=8j+g, c=16s+2t+8r+{0,1}.
__global__ void prep_wf(const float* __restrict__ W1, const float* __restrict__ W2) {
    int tidg = blockIdx.x * blockDim.x + threadIdx.x;
    const int N = KK * 512;  // hi words per layer
    if (tidg >= 2 * N) return;
    int l = (tidg >= N);
    int e = l ? (tidg - N) : tidg;
    int ij = e >> 9;
    int widx = e & 511;
    int lane = widx >> 4;
    int q = widx & 15;
    int s = q >> 3, j = (q >> 1) & 3, r = q & 1;
    int g = lane >> 2, t = lane & 3;
    int o = 8 * j + g;
    int c0 = 16 * s + 2 * t + 8 * r;
    const float* Wsrc = l ? W2 : W1;
    float v0 = Wsrc[o * (C * KK) + c0 * KK + ij];
    float v1 = Wsrc[o * (C * KK) + (c0 + 1) * KK + ij];
    uint32_t h2 = cvt_bf2(v1, v0);
    float r0 = __uint_as_float(h2 << 16);
    float r1 = __uint_as_float(h2 & 0xffff0000u);
    uint32_t l2 = cvt_bf2(v1 - r1, v0 - r0);
    uint32_t* dst = (l ? g_wf2 : g_wf1) + ij * 1024 + lane * 32;
    dst[q] = h2;
    dst[16 + q] = l2;
}

// ---------------- pad x; zero hpad borders ----------------------------------
__global__ void pad_x(const float* __restrict__ x) {
    int t = blockIdx.x * blockDim.x + threadIdx.x;
    if (t >= C * PPLANE) return;
    int c = t / PPLANE;
    int rem = t - c * PPLANE;
    int r = rem / PSTRIDE;
    int col = rem - r * PSTRIDE;
    bool interior = (r >= PAD) && (r < PAD + H) && (col >= PAD) && (col < PAD + W);
    if (interior) {
        g_xpad[t] = x[c * HW + (r - PAD) * W + (col - PAD)];
    } else {
        g_xpad[t] = 0.f;
        g_hpad[t] = 0.f;
    }
}

// ---------------- guidance kernel ------------------------------------------
__global__ void compute_k(const float* __restrict__ f) {
    int p = blockIdx.x * blockDim.x + threadIdx.x;
    int h = p >> 7;
    int w = p & 127;
    float fc[C];
#pragma unroll
    for (int c = 0; c < C; c++) fc[c] = __ldg(f + c * HW + p);
    float normc = 0.f;
#pragma unroll
    for (int c = 0; c < C; c++) normc = fmaf(fc[c], fc[c], normc);

    int ij0 = blockIdx.y * 27;
#pragma unroll 1
    for (int s = 0; s < 27; s++) {
        int ij = ij0 + s;
        int hh = h + (ij / KS) * DIL - PAD;
        int ww = w + (ij % KS) * DIL - PAD;
        float acc;
        if ((unsigned)hh < (unsigned)H && (unsigned)ww < (unsigned)W) {
            const float* fp = f + hh * W + ww;
            acc = 0.f;
#pragma unroll
            for (int c = 0; c < C; c++) {
                float d = __ldg(fp + c * HW) - fc[c];
                acc = fmaf(d, d, acc);
            }
        } else {
            acc = normc;
        }
        g_k[ij * HW + p] = __expf(-0.5f * acc);
    }
}

// ---------------- PAC conv via mma.sync (HMMA bf16, split hi/lo) ------------
// One CTA per image row h. 256 threads = 8 warps; warp w -> px rows [16w,16w+16).
// smem: 3 A slots (hi 10240 + lo 10240 each, 80B row stride) + slab.
#define ASLOT 20480
#define SSLAB (3 * ASLOT)                 // 61440
#define SMEM_TOTAL (SSLAB + 32 * PSTRIDE * 4)   // + 18432 = 79872

__global__ void __launch_bounds__(256, 1)
pacmma(const float* __restrict__ xin,       // padded input planes (base)
       const uint32_t* __restrict__ wf,     // prepacked B fragments
       const float* __restrict__ bias,
       float* __restrict__ obase, int oplane, int orow) {
    extern __shared__ char smb[];
    float* slab = (float*)(smb + SSLAB);    // [c][0..143]

    int tid = threadIdx.x;
    int wid = tid >> 5;
    int lane = tid & 31;
    int g = lane >> 2, t = lane & 3;
    int h = blockIdx.x;
    int px = tid & 127;
    int chalf = tid >> 7;

    float dacc[16];
#pragma unroll
    for (int i = 0; i < 16; i++) dacc[i] = 0.f;

    const float* kp = g_k + h * W + px;

#pragma unroll 1
    for (int di = 0; di < KS; di++) {
        __syncthreads();
        {   // stage slab: 32c x 144 floats of padded row (h + 2*di)
            const float4* src = (const float4*)(xin + (size_t)(h + 2 * di) * PSTRIDE);
            float4* dst = (float4*)slab;
#pragma unroll 1
            for (int i = tid; i < 32 * 36; i += 256) {
                int c = i / 36, q = i - c * 36;
                dst[i] = __ldg(src + (size_t)c * (PPLANE / 4) + q);
            }
        }
        __syncthreads();

#pragma unroll 1
        for (int b = 0; b < 3; b++) {
            // ---- build 3 A tiles (hi/lo) into slots 0..2 -------------------
#pragma unroll
            for (int s3 = 0; s3 < 3; s3++) {
                int dj = b * 3 + s3;
                int ij = di * KS + dj;
                float kv = __ldg(kp + (size_t)ij * HW);
                const float* zr = slab + px + 2 * dj;
                uint32_t hw[8], lw[8];
#pragma unroll
                for (int j = 0; j < 8; j++) {
                    float v0 = zr[(chalf * 16 + 2 * j) * PSTRIDE] * kv;
                    float v1 = zr[(chalf * 16 + 2 * j + 1) * PSTRIDE] * kv;
                    uint32_t h2 = cvt_bf2(v1, v0);
                    float r0 = __uint_as_float(h2 << 16);
                    float r1 = __uint_as_float(h2 & 0xffff0000u);
                    hw[j] = h2;
                    lw[j] = cvt_bf2(v1 - r1, v0 - r0);
                }
                char* ahi = smb + s3 * ASLOT + px * 80 + chalf * 32;
                *(uint4*)ahi = make_uint4(hw[0], hw[1], hw[2], hw[3]);
                *(uint4*)(ahi + 16) = make_uint4(hw[4], hw[5], hw[6], hw[7]);
                *(uint4*)(ahi + 10240) = make_uint4(lw[0], lw[1], lw[2], lw[3]);
                *(uint4*)(ahi + 10256) = make_uint4(lw[4], lw[5], lw[6], lw[7]);
            }
            __syncthreads();

            // ---- consume: 3 ij x 24 HMMA --------------------------------
#pragma unroll
            for (int s3 = 0; s3 < 3; s3++) {
                int ij = di * KS + b * 3 + s3;
                const uint4* wb = (const uint4*)(wf + (size_t)ij * 1024 + lane * 32);
                uint32_t bh[16], bl[16];
                {
                    uint4 u;
                    u = __ldg(wb + 0); bh[0]=u.x; bh[1]=u.y; bh[2]=u.z; bh[3]=u.w;
                    u = __ldg(wb + 1); bh[4]=u.x; bh[5]=u.y; bh[6]=u.z; bh[7]=u.w;
                    u = __ldg(wb + 2); bh[8]=u.x; bh[9]=u.y; bh[10]=u.z; bh[11]=u.w;
                    u = __ldg(wb + 3); bh[12]=u.x; bh[13]=u.y; bh[14]=u.z; bh[15]=u.w;
                    u = __ldg(wb + 4); bl[0]=u.x; bl[1]=u.y; bl[2]=u.z; bl[3]=u.w;
                    u = __ldg(wb + 5); bl[4]=u.x; bl[5]=u.y; bl[6]=u.z; bl[7]=u.w;
                    u = __ldg(wb + 6); bl[8]=u.x; bl[9]=u.y; bl[10]=u.z; bl[11]=u.w;
                    u = __ldg(wb + 7); bl[12]=u.x; bl[13]=u.y; bl[14]=u.z; bl[15]=u.w;
                }
                const char* ar0 = smb + s3 * ASLOT + (16 * wid + g) * 80 + t * 4;
                const char* ar1 = ar0 + 8 * 80;
#pragma unroll
                for (int s = 0; s < 2; s++) {
                    uint32_t a0 = *(const uint32_t*)(ar0 + s * 32);
                    uint32_t a1 = *(const uint32_t*)(ar1 + s * 32);
                    uint32_t a2 = *(const uint32_t*)(ar0 + s * 32 + 16);
                    uint32_t a3 = *(const uint32_t*)(ar1 + s * 32 + 16);
                    uint32_t l0 = *(const uint32_t*)(ar0 + 10240 + s * 32);
                    uint32_t l1 = *(const uint32_t*)(ar1 + 10240 + s * 32);
                    uint32_t l2 = *(const uint32_t*)(ar0 + 10240 + s * 32 + 16);
                    uint32_t l3 = *(const uint32_t*)(ar1 + 10240 + s * 32 + 16);
#pragma unroll
                    for (int j = 0; j < 4; j++) {
                        uint32_t b0 = bh[s * 8 + j * 2], b1 = bh[s * 8 + j * 2 + 1];
                        mma16816(dacc + j * 4, a0, a1, a2, a3, b0, b1);
                        mma16816(dacc + j * 4, l0, l1, l2, l3, b0, b1);
                        mma16816(dacc + j * 4, a0, a1, a2, a3,
                                 bl[s * 8 + j * 2], bl[s * 8 + j * 2 + 1]);
                    }
                }
            }
            __syncthreads();
        }
    }

    // ---- epilogue: D[g..g+8][o] + bias -> out[o][p] (sector-coalesced) ----
    float* ob = obase + (size_t)h * orow;
    int p0 = 16 * wid + g, p1 = p0 + 8;
#pragma unroll
    for (int j = 0; j < 4; j++) {
        int o0 = 8 * j + 2 * t;
        float b0 = __ldg(bias + o0), b1 = __ldg(bias + o0 + 1);
        ob[(size_t)o0 * oplane + p0] = dacc[j * 4 + 0] + b0;
        ob[(size_t)(o0 + 1) * oplane + p0] = dacc[j * 4 + 1] + b1;
        ob[(size_t)o0 * oplane + p1] = dacc[j * 4 + 2] + b0;
        ob[(size_t)(o0 + 1) * oplane + p1] = dacc[j * 4 + 3] + b1;
    }
}

// ---------------------------------------------------------------------------
extern "C" void kernel_launch(void* const* d_in, const int* in_sizes, int n_in,
                              void* d_out, int out_size) {
    const float* x = (const float*)d_in[0];
    const float* f = (const float*)d_in[1];
    const float* W1 = (const float*)d_in[2];
    const float* b1 = (const float*)d_in[3];
    const float* W2 = (const float*)d_in[4];
    const float* b2 = (const float*)d_in[5];
    float* out = (float*)d_out;

    float* xpad;   cudaGetSymbolAddress((void**)&xpad, g_xpad);
    float* hpad;   cudaGetSymbolAddress((void**)&hpad, g_hpad);
    uint32_t* wf1; cudaGetSymbolAddress((void**)&wf1, g_wf1);
    uint32_t* wf2; cudaGetSymbolAddress((void**)&wf2, g_wf2);

    cudaFuncSetAttribute(pacmma, cudaFuncAttributeMaxDynamicSharedMemorySize, SMEM_TOTAL);

    // 1. weights -> per-lane bf16 hi/lo fragments
    prep_wf<<<(2 * KK * 512 + 255) / 256, 256>>>(W1, W2);

    // 2. pad x; zero hpad borders
    pad_x<<<(C * PPLANE + 255) / 256, 256>>>(x);

    // 3. guidance kernel
    dim3 gk(HW / 256, 3);
    compute_k<<<gk, 256>>>(f);

    // 4. layer 1: xpad -> hpad interior
    pacmma<<<H, 256, SMEM_TOTAL>>>(xpad, wf1, b1,
                                   hpad + PAD * PSTRIDE + PAD, PPLANE, PSTRIDE);

    // 5. layer 2: hpad -> out
    pacmma<<<H, 256, SMEM_TOTAL>>>(hpad, wf2, b2, out, HW, W);
}